// round 5
// baseline (speedup 1.0000x reference)
#include <cuda_runtime.h>
#include <math.h>

#define N_NODES 100000
#define C 128
#define OUTC 64
#define AST 132   // padded shared stride for A tile

// ---------------- scratch (static device globals: allocation-free) ----------
// Referenced ONLY from device code (host-side use of __device__ symbols yields
// the host shadow address — that was the round-3 bug).
__device__ float g_deg[N_NODES];
__device__ float g_dinv[N_NODES];
__device__ float g_aggX[(size_t)N_NODES * C];
__device__ float g_h[(size_t)N_NODES * C];
__device__ float g_aggH[(size_t)N_NODES * C];
__device__ float g_Wcat[C * C];
__device__ float g_bcat[C];

// ---------------- degree -----------------------------------------------------
__global__ void k_deg_init() {
    int i = blockIdx.x * blockDim.x + threadIdx.x;
    if (i < N_NODES) g_deg[i] = 1.0f;   // self-loop contributes 1
}

__global__ void k_deg(const int* __restrict__ dst, int n_edges) {
    int e = blockIdx.x * blockDim.x + threadIdx.x;
    if (e < n_edges) atomicAdd(&g_deg[dst[e]], 1.0f);
}

// ---------------- self-loop term: agg[i] = dinv[i]^2 * srcmat[i] -------------
// Plain store (agg buffer needs no zeroing). PHASE 0: x -> g_aggX (+write dinv)
// PHASE 1: g_h -> g_aggH.
template<int PHASE>
__global__ void k_selfloop(const float* __restrict__ x) {
    const float* srcmat = (PHASE == 0) ? x : g_h;
    float* agg = (PHASE == 0) ? g_aggX : g_aggH;
    unsigned tid = blockIdx.x * blockDim.x + threadIdx.x;
    unsigned node = tid >> 5;
    unsigned lane = tid & 31;
    if (node >= N_NODES) return;
    float di = rsqrtf(g_deg[node]);     // deg >= 1 always
    if (PHASE == 0 && lane == 0) g_dinv[node] = di;
    float c = di * di;
    float4 v = *reinterpret_cast<const float4*>(srcmat + (size_t)node * C + lane * 4);
    v.x *= c; v.y *= c; v.z *= c; v.w *= c;
    *reinterpret_cast<float4*>(agg + (size_t)node * C + lane * 4) = v;
}

// ---------------- edge scatter: agg[dst] += dinv[src]*dinv[dst]*srcmat[src] --
// warp per edge; lane handles one float4 (4 channels); vector atomics (sm_90+)
template<int PHASE>
__global__ void k_scatter(const int* __restrict__ src, const int* __restrict__ dst,
                          const float* __restrict__ x, int n_edges) {
    const float* srcmat = (PHASE == 0) ? x : g_h;
    float* agg = (PHASE == 0) ? g_aggX : g_aggH;
    unsigned tid = blockIdx.x * blockDim.x + threadIdx.x;
    unsigned e = tid >> 5;
    unsigned lane = tid & 31;
    if (e >= (unsigned)n_edges) return;
    int s = src[e];
    int d = dst[e];
    float c = g_dinv[s] * g_dinv[d];
    float4 v = *reinterpret_cast<const float4*>(srcmat + (size_t)s * C + lane * 4);
    v.x *= c; v.y *= c; v.z *= c; v.w *= c;
    atomicAdd(reinterpret_cast<float4*>(agg + (size_t)d * C + lane * 4), v);
}

// ---------------- pack [Wmu | Wls] and [bmu | bls] ---------------------------
__global__ void k_pack(const float* __restrict__ Wmu, const float* __restrict__ Wls,
                       const float* __restrict__ bmu, const float* __restrict__ bls) {
    int tid = blockIdx.x * blockDim.x + threadIdx.x;
    if (tid < C * C) {
        int k = tid / C, j = tid % C;
        g_Wcat[tid] = (j < OUTC) ? Wmu[k * OUTC + j] : Wls[k * OUTC + (j - OUTC)];
    } else if (tid < C * C + C) {
        int j = tid - C * C;
        g_bcat[j] = (j < OUTC) ? bmu[j] : bls[j - OUTC];
    }
}

// ---------------- fused GEMM: C[m,128] = A[m,128] @ B[128,128] + bias --------
// MODE 0: A=g_aggX, B=W1(param), bias=b1(param), out=g_h;
//         epilogue = ReLU then row L2-normalize
// MODE 1: A=g_aggH, B=g_Wcat, bias=g_bcat, out=outp(param = d_out);
//         epilogue = split cols [0,64)->mu region, [64,128)->logstd region
// block: 256 threads = 16(tx cols) x 16(ty rows); micro-tile 4 rows x 8 cols,
// strided (row = ty+16i, col = tx+16j) so LDS is broadcast/conflict-free and
// each ty-group owns complete rows (enables shuffle row reduction for MODE 0).
template<int MODE>
__global__ void k_gemm(const float* __restrict__ Bp, const float* __restrict__ biasp,
                       float* __restrict__ outp) {
    const float* A    = (MODE == 0) ? g_aggX : g_aggH;
    const float* B    = (MODE == 0) ? Bp : g_Wcat;
    const float* bias = (MODE == 0) ? biasp : g_bcat;
    float* out        = (MODE == 0) ? g_h : outp;
    const int M = N_NODES;

    extern __shared__ float sm[];
    float* As = sm;             // 64 x AST
    float* Bs = sm + 64 * AST;  // 128 x 128

    int tid = threadIdx.x;
    int m0  = blockIdx.x * 64;

    // load B tile (whole 128x128)
    for (int i = tid; i < C * C / 4; i += 256)
        reinterpret_cast<float4*>(Bs)[i] = reinterpret_cast<const float4*>(B)[i];
    // load A tile (64 rows, guarded), padded stride
    for (int i = tid; i < 64 * (C / 4); i += 256) {
        int r  = i / (C / 4);
        int c4 = i % (C / 4);
        float4 v = make_float4(0.f, 0.f, 0.f, 0.f);
        if (m0 + r < M)
            v = reinterpret_cast<const float4*>(A + (size_t)(m0 + r) * C)[c4];
        reinterpret_cast<float4*>(As + r * AST)[c4] = v;
    }
    __syncthreads();

    int tx = tid & 15, ty = tid >> 4;

    float acc[4][8];
#pragma unroll
    for (int i = 0; i < 4; i++)
#pragma unroll
        for (int j = 0; j < 8; j++) acc[i][j] = 0.f;

#pragma unroll 4
    for (int k = 0; k < C; k++) {
        float a[4], b[8];
#pragma unroll
        for (int i = 0; i < 4; i++) a[i] = As[(ty + 16 * i) * AST + k];
#pragma unroll
        for (int j = 0; j < 8; j++) b[j] = Bs[k * C + tx + 16 * j];
#pragma unroll
        for (int i = 0; i < 4; i++)
#pragma unroll
            for (int j = 0; j < 8; j++) acc[i][j] = fmaf(a[i], b[j], acc[i][j]);
    }

    if (MODE == 0) {
        // bias + ReLU + row L2 normalize (second ReLU in ref is a no-op: h>=0)
#pragma unroll
        for (int i = 0; i < 4; i++) {
            float ss = 0.f;
#pragma unroll
            for (int j = 0; j < 8; j++) {
                float v = fmaxf(acc[i][j] + bias[tx + 16 * j], 0.f);
                acc[i][j] = v;
                ss += v * v;
            }
            // reduce across the 16 tx lanes (bits 0..3 of lane id)
#pragma unroll
            for (int msk = 1; msk < 16; msk <<= 1)
                ss += __shfl_xor_sync(0xffffffffu, ss, msk);
            float scale = 1.f / fmaxf(sqrtf(ss), 1e-12f);
            int r = m0 + ty + 16 * i;
            if (r < M) {
#pragma unroll
                for (int j = 0; j < 8; j++)
                    out[(size_t)r * C + tx + 16 * j] = acc[i][j] * scale;
            }
        }
    } else {
        // split epilogue: cols [0,64) -> mu, [64,128) -> logstd
#pragma unroll
        for (int i = 0; i < 4; i++) {
            int r = m0 + ty + 16 * i;
            if (r < M) {
#pragma unroll
                for (int j = 0; j < 8; j++) {
                    int c = tx + 16 * j;
                    float v = acc[i][j] + bias[c];
                    size_t off = (c < OUTC)
                        ? (size_t)r * OUTC + c
                        : (size_t)N_NODES * OUTC + (size_t)r * OUTC + (c - OUTC);
                    out[off] = v;
                }
            }
        }
    }
}

// ---------------- launch -----------------------------------------------------
extern "C" void kernel_launch(void* const* d_in, const int* in_sizes, int n_in,
                              void* d_out, int out_size) {
    const float* x   = (const float*)d_in[0];
    const int*   ei  = (const int*)  d_in[1];
    const float* W1  = (const float*)d_in[2];
    const float* b1  = (const float*)d_in[3];
    const float* Wmu = (const float*)d_in[4];
    const float* bmu = (const float*)d_in[5];
    const float* Wls = (const float*)d_in[6];
    const float* bls = (const float*)d_in[7];
    float* out = (float*)d_out;

    const int n_edges = in_sizes[1] / 2;     // edge_index is [2, E]
    const int* src = ei;                     // edge_index[0]
    const int* dst = ei + n_edges;           // edge_index[1]

    const int smem = (64 * AST + C * C) * (int)sizeof(float);  // ~99 KB

    static bool configured = false;
    if (!configured) {
        cudaFuncSetAttribute(k_gemm<0>, cudaFuncAttributeMaxDynamicSharedMemorySize, smem);
        cudaFuncSetAttribute(k_gemm<1>, cudaFuncAttributeMaxDynamicSharedMemorySize, smem);
        configured = true;
    }

    // 1) degrees + dinv
    k_deg_init<<<(N_NODES + 255) / 256, 256>>>();
    k_deg<<<(n_edges + 255) / 256, 256>>>(dst, n_edges);

    // 2) aggX = D^-1/2 A_hat D^-1/2 @ x  (self-loop store, then edge atomics)
    {
        unsigned t = (unsigned)N_NODES * 32u;
        k_selfloop<0><<<(t + 255) / 256, 256>>>(x);
    }
    {
        unsigned t = (unsigned)n_edges * 32u;
        k_scatter<0><<<(t + 255) / 256, 256>>>(src, dst, x, n_edges);
    }

    // 3) h = rownorm(relu(aggX @ W1 + b1))
    k_gemm<0><<<(N_NODES + 63) / 64, 256, smem>>>(W1, b1, nullptr);

    // 4) aggH = A_norm @ h
    {
        unsigned t = (unsigned)N_NODES * 32u;
        k_selfloop<1><<<(t + 255) / 256, 256>>>(nullptr);
    }
    {
        unsigned t = (unsigned)n_edges * 32u;
        k_scatter<1><<<(t + 255) / 256, 256>>>(src, dst, nullptr, n_edges);
    }

    // 5) [mu | logstd] = aggH @ [Wmu | Wls] + [bmu | bls]
    k_pack<<<(C * C + C + 255) / 256, 256>>>(Wmu, Wls, bmu, bls);
    k_gemm<1><<<(N_NODES + 63) / 64, 256, smem>>>(nullptr, nullptr, out);
}

// round 6
// speedup vs baseline: 1.1040x; 1.1040x over previous
#include <cuda_runtime.h>
#include <math.h>

#define N_NODES 100000
#define E_MAX   1600000
#define C 128
#define OUTC 64
#define AST 132          // padded shared stride for A tile
#define SCAN_BS 1024
#define SCAN_NB ((N_NODES + SCAN_BS - 1) / SCAN_BS)   // 98

// ---------------- scratch (static device globals: allocation-free) ----------
// Referenced ONLY from device code (host-side use of __device__ symbols gives
// the host shadow address — round-3 lesson).
__device__ int   g_cnt[N_NODES];        // in-degree (edges only, no self-loop)
__device__ int   g_rowstart[N_NODES];   // CSR row offsets (exclusive scan)
__device__ int   g_cursor[N_NODES];     // fill cursors
__device__ int   g_bsum[SCAN_NB];       // scan block sums
__device__ int   g_boff[SCAN_NB];       // scan block offsets
__device__ int   g_csrc[E_MAX];         // CSR: src node per incoming edge slot
__device__ float g_dinv[N_NODES];
__device__ float g_aggX[(size_t)N_NODES * C];
__device__ float g_h[(size_t)N_NODES * C];
__device__ float g_aggH[(size_t)N_NODES * C];
__device__ float g_Wcat[C * C];
__device__ float g_bcat[C];

// ---------------- CSR build --------------------------------------------------
__global__ void k_cnt_init() {
    int i = blockIdx.x * blockDim.x + threadIdx.x;
    if (i < N_NODES) g_cnt[i] = 0;
}

__global__ void k_count(const int* __restrict__ dst, int n_edges) {
    int e = blockIdx.x * blockDim.x + threadIdx.x;
    if (e < n_edges) atomicAdd(&g_cnt[dst[e]], 1);
}

// pass 1: per-block inclusive scan -> exclusive per element + block sums
__global__ void k_scan_block() {
    __shared__ int sh[SCAN_BS];
    int tid = threadIdx.x;
    int i = blockIdx.x * SCAN_BS + tid;
    int v = (i < N_NODES) ? g_cnt[i] : 0;
    sh[tid] = v;
    __syncthreads();
#pragma unroll
    for (int off = 1; off < SCAN_BS; off <<= 1) {
        int t = (tid >= off) ? sh[tid - off] : 0;
        __syncthreads();
        sh[tid] += t;
        __syncthreads();
    }
    if (i < N_NODES) g_rowstart[i] = sh[tid] - v;   // exclusive
    if (tid == SCAN_BS - 1) g_bsum[blockIdx.x] = sh[tid];
}

// pass 2: single block scans the block sums (SCAN_NB <= 128)
__global__ void k_scan_bsum() {
    __shared__ int sh[128];
    int tid = threadIdx.x;
    int v = (tid < SCAN_NB) ? g_bsum[tid] : 0;
    sh[tid] = v;
    __syncthreads();
#pragma unroll
    for (int off = 1; off < 128; off <<= 1) {
        int t = (tid >= off) ? sh[tid - off] : 0;
        __syncthreads();
        sh[tid] += t;
        __syncthreads();
    }
    if (tid < SCAN_NB) g_boff[tid] = sh[tid] - v;   // exclusive
}

// pass 3: add block offsets; init cursors; compute dinv (deg = cnt + selfloop)
__global__ void k_scan_add() {
    int i = blockIdx.x * blockDim.x + threadIdx.x;
    if (i >= N_NODES) return;
    g_rowstart[i] += g_boff[i >> 10];
    g_cursor[i] = 0;
    g_dinv[i] = rsqrtf((float)g_cnt[i] + 1.0f);
}

__global__ void k_fill(const int* __restrict__ src, const int* __restrict__ dst,
                       int n_edges) {
    int e = blockIdx.x * blockDim.x + threadIdx.x;
    if (e >= n_edges) return;
    int d = dst[e];
    int p = atomicAdd(&g_cursor[d], 1);
    g_csrc[g_rowstart[d] + p] = src[e];
}

// ---------------- gather-aggregate: one warp per destination node ------------
// agg[n] = dinv[n]^2 * srcmat[n] + sum_{s in in(n)} dinv[n]*dinv[s]*srcmat[s]
// PHASE 0: x -> g_aggX     PHASE 1: g_h -> g_aggH
template<int PHASE>
__global__ void k_agg(const float* __restrict__ x) {
    const float* srcmat = (PHASE == 0) ? x : g_h;
    float* agg = (PHASE == 0) ? g_aggX : g_aggH;

    unsigned node = (blockIdx.x * blockDim.x + threadIdx.x) >> 5;
    unsigned lane = threadIdx.x & 31;
    if (node >= N_NODES) return;

    float din = g_dinv[node];
    // self-loop init
    float4 acc = reinterpret_cast<const float4*>(srcmat + (size_t)node * C)[lane];
    float cself = din * din;
    acc.x *= cself; acc.y *= cself; acc.z *= cself; acc.w *= cself;

    int beg = g_rowstart[node];
    int cnt = g_cnt[node];
    int j = 0;
    // 2-way unrolled edge loop for MLP
    for (; j + 1 < cnt; j += 2) {
        int s0 = g_csrc[beg + j];
        int s1 = g_csrc[beg + j + 1];
        float c0 = din * g_dinv[s0];
        float c1 = din * g_dinv[s1];
        float4 v0 = reinterpret_cast<const float4*>(srcmat + (size_t)s0 * C)[lane];
        float4 v1 = reinterpret_cast<const float4*>(srcmat + (size_t)s1 * C)[lane];
        acc.x += c0 * v0.x + c1 * v1.x;
        acc.y += c0 * v0.y + c1 * v1.y;
        acc.z += c0 * v0.z + c1 * v1.z;
        acc.w += c0 * v0.w + c1 * v1.w;
    }
    if (j < cnt) {
        int s = g_csrc[beg + j];
        float c = din * g_dinv[s];
        float4 v = reinterpret_cast<const float4*>(srcmat + (size_t)s * C)[lane];
        acc.x += c * v.x; acc.y += c * v.y; acc.z += c * v.z; acc.w += c * v.w;
    }
    reinterpret_cast<float4*>(agg + (size_t)node * C)[lane] = acc;
}

// ---------------- pack [Wmu | Wls] and [bmu | bls] ---------------------------
__global__ void k_pack(const float* __restrict__ Wmu, const float* __restrict__ Wls,
                       const float* __restrict__ bmu, const float* __restrict__ bls) {
    int tid = blockIdx.x * blockDim.x + threadIdx.x;
    if (tid < C * C) {
        int k = tid / C, j = tid % C;
        g_Wcat[tid] = (j < OUTC) ? Wmu[k * OUTC + j] : Wls[k * OUTC + (j - OUTC)];
    } else if (tid < C * C + C) {
        int j = tid - C * C;
        g_bcat[j] = (j < OUTC) ? bmu[j] : bls[j - OUTC];
    }
}

// ---------------- fused GEMM: C[m,128] = A[m,128] @ B[128,128] + bias --------
// MODE 0: A=g_aggX, B=W1(param), bias=b1(param), out=g_h;
//         epilogue = ReLU then row L2-normalize
// MODE 1: A=g_aggH, B=g_Wcat, bias=g_bcat, out=outp(param = d_out);
//         epilogue = split cols [0,64)->mu region, [64,128)->logstd region
template<int MODE>
__global__ void k_gemm(const float* __restrict__ Bp, const float* __restrict__ biasp,
                       float* __restrict__ outp) {
    const float* A    = (MODE == 0) ? g_aggX : g_aggH;
    const float* B    = (MODE == 0) ? Bp : g_Wcat;
    const float* bias = (MODE == 0) ? biasp : g_bcat;
    float* out        = (MODE == 0) ? g_h : outp;
    const int M = N_NODES;

    extern __shared__ float sm[];
    float* As = sm;             // 64 x AST
    float* Bs = sm + 64 * AST;  // 128 x 128

    int tid = threadIdx.x;
    int m0  = blockIdx.x * 64;

    for (int i = tid; i < C * C / 4; i += 256)
        reinterpret_cast<float4*>(Bs)[i] = reinterpret_cast<const float4*>(B)[i];
    for (int i = tid; i < 64 * (C / 4); i += 256) {
        int r  = i / (C / 4);
        int c4 = i % (C / 4);
        float4 v = make_float4(0.f, 0.f, 0.f, 0.f);
        if (m0 + r < M)
            v = reinterpret_cast<const float4*>(A + (size_t)(m0 + r) * C)[c4];
        reinterpret_cast<float4*>(As + r * AST)[c4] = v;
    }
    __syncthreads();

    int tx = tid & 15, ty = tid >> 4;

    float acc[4][8];
#pragma unroll
    for (int i = 0; i < 4; i++)
#pragma unroll
        for (int j = 0; j < 8; j++) acc[i][j] = 0.f;

#pragma unroll 4
    for (int k = 0; k < C; k++) {
        float a[4], b[8];
#pragma unroll
        for (int i = 0; i < 4; i++) a[i] = As[(ty + 16 * i) * AST + k];
#pragma unroll
        for (int j = 0; j < 8; j++) b[j] = Bs[k * C + tx + 16 * j];
#pragma unroll
        for (int i = 0; i < 4; i++)
#pragma unroll
            for (int j = 0; j < 8; j++) acc[i][j] = fmaf(a[i], b[j], acc[i][j]);
    }

    if (MODE == 0) {
#pragma unroll
        for (int i = 0; i < 4; i++) {
            float ss = 0.f;
#pragma unroll
            for (int j = 0; j < 8; j++) {
                float v = fmaxf(acc[i][j] + bias[tx + 16 * j], 0.f);
                acc[i][j] = v;
                ss += v * v;
            }
#pragma unroll
            for (int msk = 1; msk < 16; msk <<= 1)
                ss += __shfl_xor_sync(0xffffffffu, ss, msk);
            float scale = 1.f / fmaxf(sqrtf(ss), 1e-12f);
            int r = m0 + ty + 16 * i;
            if (r < M) {
#pragma unroll
                for (int j = 0; j < 8; j++)
                    out[(size_t)r * C + tx + 16 * j] = acc[i][j] * scale;
            }
        }
    } else {
#pragma unroll
        for (int i = 0; i < 4; i++) {
            int r = m0 + ty + 16 * i;
            if (r < M) {
#pragma unroll
                for (int j = 0; j < 8; j++) {
                    int c = tx + 16 * j;
                    float v = acc[i][j] + bias[c];
                    size_t off = (c < OUTC)
                        ? (size_t)r * OUTC + c
                        : (size_t)N_NODES * OUTC + (size_t)r * OUTC + (c - OUTC);
                    out[off] = v;
                }
            }
        }
    }
}

// ---------------- launch -----------------------------------------------------
extern "C" void kernel_launch(void* const* d_in, const int* in_sizes, int n_in,
                              void* d_out, int out_size) {
    const float* x   = (const float*)d_in[0];
    const int*   ei  = (const int*)  d_in[1];
    const float* W1  = (const float*)d_in[2];
    const float* b1  = (const float*)d_in[3];
    const float* Wmu = (const float*)d_in[4];
    const float* bmu = (const float*)d_in[5];
    const float* Wls = (const float*)d_in[6];
    const float* bls = (const float*)d_in[7];
    float* out = (float*)d_out;

    const int n_edges = in_sizes[1] / 2;     // edge_index is [2, E]
    const int* src = ei;                     // edge_index[0]
    const int* dst = ei + n_edges;           // edge_index[1]

    const int smem = (64 * AST + C * C) * (int)sizeof(float);  // ~99 KB

    static bool configured = false;
    if (!configured) {
        cudaFuncSetAttribute(k_gemm<0>, cudaFuncAttributeMaxDynamicSharedMemorySize, smem);
        cudaFuncSetAttribute(k_gemm<1>, cudaFuncAttributeMaxDynamicSharedMemorySize, smem);
        configured = true;
    }

    // ---- CSR build (once, reused by both aggregations) ----
    k_cnt_init<<<(N_NODES + 255) / 256, 256>>>();
    k_count<<<(n_edges + 255) / 256, 256>>>(dst, n_edges);
    k_scan_block<<<SCAN_NB, SCAN_BS>>>();
    k_scan_bsum<<<1, 128>>>();
    k_scan_add<<<(N_NODES + 255) / 256, 256>>>();
    k_fill<<<(n_edges + 255) / 256, 256>>>(src, dst, n_edges);

    // ---- layer 1: aggX = A_norm @ x ; h = rownorm(relu(aggX @ W1 + b1)) ----
    {
        unsigned t = (unsigned)N_NODES * 32u;
        k_agg<0><<<(t + 255) / 256, 256>>>(x);
    }
    k_gemm<0><<<(N_NODES + 63) / 64, 256, smem>>>(W1, b1, nullptr);

    // ---- layer 2: aggH = A_norm @ h ; [mu|logstd] = aggH @ Wcat + bcat ----
    {
        unsigned t = (unsigned)N_NODES * 32u;
        k_agg<1><<<(t + 255) / 256, 256>>>(nullptr);
    }
    k_pack<<<(C * C + C + 255) / 256, 256>>>(Wmu, Wls, bmu, bls);
    k_gemm<1><<<(N_NODES + 63) / 64, 256, smem>>>(nullptr, nullptr, out);
}

// round 7
// speedup vs baseline: 1.4096x; 1.2768x over previous
#include <cuda_runtime.h>
#include <math.h>

#define N_NODES 100000
#define E_MAX   1600000
#define C 128
#define OUTC 64
#define AST 132          // padded shared stride for A tile (132 = 4*33, float4 ok)
#define SCAN_BS 1024
#define SCAN_NB ((N_NODES + SCAN_BS - 1) / SCAN_BS)   // 98

// ---------------- scratch (static device globals: allocation-free) ----------
// Referenced ONLY from device code (host-side use of __device__ symbols gives
// the host shadow address — round-3 lesson).
__device__ int   g_cnt[N_NODES];        // in-degree (edges only, no self-loop)
__device__ int   g_rowstart[N_NODES];   // CSR row offsets (exclusive scan)
__device__ int   g_cursor[N_NODES];     // fill cursors
__device__ int   g_bsum[SCAN_NB];       // scan block sums
__device__ int   g_csrc[E_MAX];         // CSR: src node per incoming edge slot
__device__ float g_dinv[N_NODES];
__device__ float g_aggX[(size_t)N_NODES * C];
__device__ float g_h[(size_t)N_NODES * C];
__device__ float g_aggH[(size_t)N_NODES * C];

// ---------------- CSR build --------------------------------------------------
__global__ void k_cnt_init() {
    int i = blockIdx.x * blockDim.x + threadIdx.x;
    if (i < N_NODES) g_cnt[i] = 0;
}

__global__ void k_count(const int* __restrict__ dst, int n_edges) {
    int e = blockIdx.x * blockDim.x + threadIdx.x;
    if (e < n_edges) atomicAdd(&g_cnt[dst[e]], 1);
}

// pass 1: per-block inclusive scan -> exclusive per element + block sums
__global__ void k_scan_block() {
    __shared__ int sh[SCAN_BS];
    int tid = threadIdx.x;
    int i = blockIdx.x * SCAN_BS + tid;
    int v = (i < N_NODES) ? g_cnt[i] : 0;
    sh[tid] = v;
    __syncthreads();
#pragma unroll
    for (int off = 1; off < SCAN_BS; off <<= 1) {
        int t = (tid >= off) ? sh[tid - off] : 0;
        __syncthreads();
        sh[tid] += t;
        __syncthreads();
    }
    if (i < N_NODES) g_rowstart[i] = sh[tid] - v;   // exclusive
    if (tid == SCAN_BS - 1) g_bsum[blockIdx.x] = sh[tid];
}

// pass 2 (merged): each 256-thread block covers nodes [b*256, b*256+256) which
// all lie in scan-block sb = b>>2; reduce g_bsum[0..sb-1] locally, add offset,
// init cursors, compute dinv. (98 sums max — cheap per block.)
__global__ void k_scan_add() {
    __shared__ int ssum[128];
    int tid = threadIdx.x;
    int sb = blockIdx.x >> 2;   // 1024/256 = 4 blocks per scan-block, aligned
    if (tid < 128) ssum[tid] = (tid < sb) ? g_bsum[tid] : 0;
    __syncthreads();
#pragma unroll
    for (int s = 64; s > 0; s >>= 1) {
        if (tid < s) ssum[tid] += ssum[tid + s];
        __syncthreads();
    }
    int off = ssum[0];
    int i = blockIdx.x * 256 + tid;
    if (i < N_NODES) {
        g_rowstart[i] += off;
        g_cursor[i] = 0;
        g_dinv[i] = rsqrtf((float)g_cnt[i] + 1.0f);
    }
}

__global__ void k_fill(const int* __restrict__ src, const int* __restrict__ dst,
                       int n_edges) {
    int e = blockIdx.x * blockDim.x + threadIdx.x;
    if (e >= n_edges) return;
    int d = dst[e];
    int p = atomicAdd(&g_cursor[d], 1);
    g_csrc[g_rowstart[d] + p] = src[e];
}

// ---------------- gather-aggregate: one warp per destination node ------------
// agg[n] = dinv[n]^2 * srcmat[n] + sum_{s in in(n)} dinv[n]*dinv[s]*srcmat[s]
// PHASE 0: x -> g_aggX     PHASE 1: g_h -> g_aggH
template<int PHASE>
__global__ void k_agg(const float* __restrict__ x) {
    const float* srcmat = (PHASE == 0) ? x : g_h;
    float* agg = (PHASE == 0) ? g_aggX : g_aggH;

    unsigned node = (blockIdx.x * blockDim.x + threadIdx.x) >> 5;
    unsigned lane = threadIdx.x & 31;
    if (node >= N_NODES) return;

    float din = g_dinv[node];
    // self-loop init
    float4 acc = reinterpret_cast<const float4*>(srcmat + (size_t)node * C)[lane];
    float cself = din * din;
    acc.x *= cself; acc.y *= cself; acc.z *= cself; acc.w *= cself;

    int beg = g_rowstart[node];
    int cnt = g_cnt[node];
    int j = 0;
    // 4-way unrolled edge loop: 4 rows in flight per warp (MLP)
    for (; j + 3 < cnt; j += 4) {
        int s0 = g_csrc[beg + j];
        int s1 = g_csrc[beg + j + 1];
        int s2 = g_csrc[beg + j + 2];
        int s3 = g_csrc[beg + j + 3];
        float c0 = din * g_dinv[s0];
        float c1 = din * g_dinv[s1];
        float c2 = din * g_dinv[s2];
        float c3 = din * g_dinv[s3];
        float4 v0 = reinterpret_cast<const float4*>(srcmat + (size_t)s0 * C)[lane];
        float4 v1 = reinterpret_cast<const float4*>(srcmat + (size_t)s1 * C)[lane];
        float4 v2 = reinterpret_cast<const float4*>(srcmat + (size_t)s2 * C)[lane];
        float4 v3 = reinterpret_cast<const float4*>(srcmat + (size_t)s3 * C)[lane];
        acc.x += c0 * v0.x + c1 * v1.x + c2 * v2.x + c3 * v3.x;
        acc.y += c0 * v0.y + c1 * v1.y + c2 * v2.y + c3 * v3.y;
        acc.z += c0 * v0.z + c1 * v1.z + c2 * v2.z + c3 * v3.z;
        acc.w += c0 * v0.w + c1 * v1.w + c2 * v2.w + c3 * v3.w;
    }
    for (; j < cnt; j++) {
        int s = g_csrc[beg + j];
        float c = din * g_dinv[s];
        float4 v = reinterpret_cast<const float4*>(srcmat + (size_t)s * C)[lane];
        acc.x += c * v.x; acc.y += c * v.y; acc.z += c * v.z; acc.w += c * v.w;
    }
    reinterpret_cast<float4*>(agg + (size_t)node * C)[lane] = acc;
}

// ---------------- fused GEMM: out[m,128] = A[m,128] @ B[128,128] + bias ------
// 128x128 block tile, 256 threads (16 tx x 16 ty), 8x8 microtile:
// rows ty+16i (i<8), cols tx+16j (j<8). Per k: 16 scalar LDS / 64 FMA =
// 128 B/cyc crossbar (exactly the cap); 1-step software pipeline hides LDS lat.
// MODE 0: A=g_aggX, B=W1, bias=b1, out=g_h; epilogue ReLU + row L2-normalize.
// MODE 1: A=g_aggH, B=[Wmu|Wls] (loaded inline), bias=[bmu|bls],
//         out=d_out split into mu / logstd regions.
template<int MODE>
__global__ void __launch_bounds__(256)
k_gemm(const float* __restrict__ Bp, const float* __restrict__ Bp2,
       const float* __restrict__ biasp, const float* __restrict__ biasp2,
       float* __restrict__ outp) {
    const float* A = (MODE == 0) ? g_aggX : g_aggH;
    float* out     = (MODE == 0) ? g_h : outp;
    const int M = N_NODES;

    extern __shared__ float sm[];
    float* As = sm;             // 128 x AST
    float* Bs = sm + 128 * AST; // 128 x 128

    int tid = threadIdx.x;
    int m0  = blockIdx.x * 128;

    // load B tile (128x128). MODE 1 concatenates Wmu|Wls on the fly
    // (each float4 lies wholly in one 64-col half).
    for (int i = tid; i < C * C / 4; i += 256) {
        float4 v;
        if (MODE == 0) {
            v = reinterpret_cast<const float4*>(Bp)[i];
        } else {
            int k = i >> 5;          // row
            int c4 = (i & 31) * 4;   // col
            v = (c4 < OUTC)
                ? *reinterpret_cast<const float4*>(Bp  + k * OUTC + c4)
                : *reinterpret_cast<const float4*>(Bp2 + k * OUTC + (c4 - OUTC));
        }
        reinterpret_cast<float4*>(Bs)[i] = v;
    }
    // load A tile (128 rows, guarded), padded stride
    for (int i = tid; i < 128 * (C / 4); i += 256) {
        int r  = i >> 5;
        int c4 = i & 31;
        float4 v = make_float4(0.f, 0.f, 0.f, 0.f);
        if (m0 + r < M)
            v = reinterpret_cast<const float4*>(A + (size_t)(m0 + r) * C)[c4];
        reinterpret_cast<float4*>(As + r * AST)[c4] = v;
    }
    __syncthreads();

    int tx = tid & 15, ty = tid >> 4;

    float acc[8][8];
#pragma unroll
    for (int i = 0; i < 8; i++)
#pragma unroll
        for (int j = 0; j < 8; j++) acc[i][j] = 0.f;

    float a_cur[8], b_cur[8];
#pragma unroll
    for (int i = 0; i < 8; i++) a_cur[i] = As[(ty + 16 * i) * AST];
#pragma unroll
    for (int j = 0; j < 8; j++) b_cur[j] = Bs[tx + 16 * j];

#pragma unroll 2
    for (int k = 0; k < C - 1; k++) {
        float a_nxt[8], b_nxt[8];
#pragma unroll
        for (int i = 0; i < 8; i++) a_nxt[i] = As[(ty + 16 * i) * AST + k + 1];
#pragma unroll
        for (int j = 0; j < 8; j++) b_nxt[j] = Bs[(k + 1) * C + tx + 16 * j];
#pragma unroll
        for (int i = 0; i < 8; i++)
#pragma unroll
            for (int j = 0; j < 8; j++)
                acc[i][j] = fmaf(a_cur[i], b_cur[j], acc[i][j]);
#pragma unroll
        for (int i = 0; i < 8; i++) a_cur[i] = a_nxt[i];
#pragma unroll
        for (int j = 0; j < 8; j++) b_cur[j] = b_nxt[j];
    }
#pragma unroll
    for (int i = 0; i < 8; i++)
#pragma unroll
        for (int j = 0; j < 8; j++)
            acc[i][j] = fmaf(a_cur[i], b_cur[j], acc[i][j]);

    if (MODE == 0) {
        // bias + ReLU + row L2 normalize (second ReLU in ref is a no-op: h>=0)
#pragma unroll
        for (int i = 0; i < 8; i++) {
            float ss = 0.f;
#pragma unroll
            for (int j = 0; j < 8; j++) {
                float v = fmaxf(acc[i][j] + biasp[tx + 16 * j], 0.f);
                acc[i][j] = v;
                ss += v * v;
            }
            // reduce across the 16 tx lanes (bits 0..3 of lane id)
#pragma unroll
            for (int msk = 1; msk < 16; msk <<= 1)
                ss += __shfl_xor_sync(0xffffffffu, ss, msk);
            float scale = 1.f / fmaxf(sqrtf(ss), 1e-12f);
            int r = m0 + ty + 16 * i;
            if (r < M) {
#pragma unroll
                for (int j = 0; j < 8; j++)
                    out[(size_t)r * C + tx + 16 * j] = acc[i][j] * scale;
            }
        }
    } else {
        // split epilogue: cols [0,64) -> mu, [64,128) -> logstd
#pragma unroll
        for (int i = 0; i < 8; i++) {
            int r = m0 + ty + 16 * i;
            if (r < M) {
#pragma unroll
                for (int j = 0; j < 8; j++) {
                    int c = tx + 16 * j;
                    float bias = (c < OUTC) ? biasp[c] : biasp2[c - OUTC];
                    float v = acc[i][j] + bias;
                    size_t off = (c < OUTC)
                        ? (size_t)r * OUTC + c
                        : (size_t)N_NODES * OUTC + (size_t)r * OUTC + (c - OUTC);
                    out[off] = v;
                }
            }
        }
    }
}

// ---------------- launch -----------------------------------------------------
extern "C" void kernel_launch(void* const* d_in, const int* in_sizes, int n_in,
                              void* d_out, int out_size) {
    const float* x   = (const float*)d_in[0];
    const int*   ei  = (const int*)  d_in[1];
    const float* W1  = (const float*)d_in[2];
    const float* b1  = (const float*)d_in[3];
    const float* Wmu = (const float*)d_in[4];
    const float* bmu = (const float*)d_in[5];
    const float* Wls = (const float*)d_in[6];
    const float* bls = (const float*)d_in[7];
    float* out = (float*)d_out;

    const int n_edges = in_sizes[1] / 2;     // edge_index is [2, E]
    const int* src = ei;                     // edge_index[0]
    const int* dst = ei + n_edges;           // edge_index[1]

    const int smem = (128 * AST + C * C) * (int)sizeof(float);  // ~130 KB

    static bool configured = false;
    if (!configured) {
        cudaFuncSetAttribute(k_gemm<0>, cudaFuncAttributeMaxDynamicSharedMemorySize, smem);
        cudaFuncSetAttribute(k_gemm<1>, cudaFuncAttributeMaxDynamicSharedMemorySize, smem);
        configured = true;
    }

    // ---- CSR build (once, reused by both aggregations) ----
    k_cnt_init<<<(N_NODES + 255) / 256, 256>>>();
    k_count<<<(n_edges + 255) / 256, 256>>>(dst, n_edges);
    k_scan_block<<<SCAN_NB, SCAN_BS>>>();
    k_scan_add<<<(N_NODES + 255) / 256, 256>>>();
    k_fill<<<(n_edges + 255) / 256, 256>>>(src, dst, n_edges);

    // ---- layer 1: aggX = A_norm @ x ; h = rownorm(relu(aggX @ W1 + b1)) ----
    {
        unsigned t = (unsigned)N_NODES * 32u;
        k_agg<0><<<(t + 255) / 256, 256>>>(x);
    }
    k_gemm<0><<<(N_NODES + 127) / 128, 256, smem>>>(W1, nullptr, b1, nullptr, nullptr);

    // ---- layer 2: aggH = A_norm @ h ; [mu|logstd] = aggH @ [Wmu|Wls] + b ----
    {
        unsigned t = (unsigned)N_NODES * 32u;
        k_agg<1><<<(t + 255) / 256, 256>>>(nullptr);
    }
    k_gemm<1><<<(N_NODES + 127) / 128, 256, smem>>>(Wmu, Wls, bmu, bls, out);
}